// round 15
// baseline (speedup 1.0000x reference)
#include <cuda_runtime.h>
#include <cuda_fp16.h>
#include <cuda_pipeline.h>
#include <math.h>

#define B 65536
#define N 512
#define EPSF 1e-8f
#define BLOCKS1 1024
#define BLOCKS2 1024
#define RPW 8   // rows per warp in pass1 (8 warps/block)

// ---------------- scratch (device globals; no allocation allowed) ----------
__device__ __align__(16) float  g_sim[B];              // 256 KB
__device__ __align__(16) __half g_E[(size_t)B * N];    // 64 MB: anchors_prob fp16
__device__ float g_colpart[BLOCKS1 * N];               // 2 MB
__device__ float g_colsum[N];
__device__ float g_thirdpart[BLOCKS2];
__device__ float g_clpart[BLOCKS2];
__device__ float g_sopart[BLOCKS2];
__device__ unsigned int g_count = 0;

__device__ __forceinline__ float warp_max(float v) {
#pragma unroll
    for (int o = 16; o; o >>= 1) v = fmaxf(v, __shfl_xor_sync(0xffffffffu, v, o));
    return v;
}

// ---------------------------------------------------------------------------
// Pass 1: per-row softmax of anchors & neighbors, sim[row], fp16 anchors_prob,
// and per-block column partial sums. A/Nb read with __ldcs (streaming).
// (unchanged from R14 — measured 50.6us)
// ---------------------------------------------------------------------------
__global__ void __launch_bounds__(256, 2) pass1_kernel(const float* __restrict__ A,
                                                       const float* __restrict__ Nb) {
    const int warp = threadIdx.x >> 5;
    const int lane = threadIdx.x & 31;
    const int base = (blockIdx.x * 8 + warp) * RPW;

    float4 colacc[4];
#pragma unroll
    for (int c = 0; c < 4; c++) colacc[c] = make_float4(0.f, 0.f, 0.f, 0.f);

    float4 ca[4], cb[4];
    {
        const float4* a4 = reinterpret_cast<const float4*>(A  + (size_t)base * N) + lane;
        const float4* n4 = reinterpret_cast<const float4*>(Nb + (size_t)base * N) + lane;
#pragma unroll
        for (int c = 0; c < 4; c++) { ca[c] = __ldcs(&a4[c * 32]); cb[c] = __ldcs(&n4[c * 32]); }
    }

#pragma unroll
    for (int r = 0; r < RPW; r++) {
        const int row = base + r;

        float4 na[4], nb4[4];
        if (r + 1 < RPW) {
            const float4* a4 = reinterpret_cast<const float4*>(A  + (size_t)(row + 1) * N) + lane;
            const float4* n4 = reinterpret_cast<const float4*>(Nb + (size_t)(row + 1) * N) + lane;
#pragma unroll
            for (int c = 0; c < 4; c++) { na[c] = __ldcs(&a4[c * 32]); nb4[c] = __ldcs(&n4[c * 32]); }
        }

        float ma = -1e30f, mn = -1e30f;
#pragma unroll
        for (int c = 0; c < 4; c++) {
            ma = fmaxf(ma, fmaxf(fmaxf(ca[c].x, ca[c].y), fmaxf(ca[c].z, ca[c].w)));
            mn = fmaxf(mn, fmaxf(fmaxf(cb[c].x, cb[c].y), fmaxf(cb[c].z, cb[c].w)));
        }
        ma = warp_max(ma);
        mn = warp_max(mn);

        float sa0 = 0.f, sa1 = 0.f, sb0 = 0.f, sb1 = 0.f, sd0 = 0.f, sd1 = 0.f;
        float4 ea[4];
#pragma unroll
        for (int c = 0; c < 4; c++) {
            ea[c].x = __expf(ca[c].x - ma); ea[c].y = __expf(ca[c].y - ma);
            ea[c].z = __expf(ca[c].z - ma); ea[c].w = __expf(ca[c].w - ma);
            float ex = __expf(cb[c].x - mn), ey = __expf(cb[c].y - mn);
            float ez = __expf(cb[c].z - mn), ew = __expf(cb[c].w - mn);
            sa0 += ea[c].x + ea[c].y;  sa1 += ea[c].z + ea[c].w;
            sb0 += ex + ey;            sb1 += ez + ew;
            sd0 += ea[c].x * ex + ea[c].y * ey;
            sd1 += ea[c].z * ez + ea[c].w * ew;
        }
        float sa = sa0 + sa1, sb = sb0 + sb1, sd = sd0 + sd1;
#pragma unroll
        for (int o = 16; o; o >>= 1) {
            sa += __shfl_xor_sync(0xffffffffu, sa, o);
            sb += __shfl_xor_sync(0xffffffffu, sb, o);
            sd += __shfl_xor_sync(0xffffffffu, sd, o);
        }

        const float inv = 1.f / sa;
        if (lane == 0) g_sim[row] = sd / (sa * sb);

#pragma unroll
        for (int c = 0; c < 4; c++) {
            float px = ea[c].x * inv, py = ea[c].y * inv;
            float pz = ea[c].z * inv, pw = ea[c].w * inv;
            colacc[c].x += px; colacc[c].y += py;
            colacc[c].z += pz; colacc[c].w += pw;
            __half2 h0 = __floats2half2_rn(px, py);
            __half2 h1 = __floats2half2_rn(pz, pw);
            float2 pk = make_float2(__uint_as_float(*reinterpret_cast<unsigned int*>(&h0)),
                                    __uint_as_float(*reinterpret_cast<unsigned int*>(&h1)));
            *reinterpret_cast<float2*>(g_E + (size_t)row * N + c * 128 + 4 * lane) = pk;
        }

#pragma unroll
        for (int c = 0; c < 4; c++) { ca[c] = na[c]; cb[c] = nb4[c]; }
    }

    __shared__ float scol[8][N];                 // 16 KB
#pragma unroll
    for (int c = 0; c < 4; c++)
        *reinterpret_cast<float4*>(&scol[warp][c * 128 + 4 * lane]) = colacc[c];
    __syncthreads();

    for (int col = threadIdx.x; col < N; col += 256) {
        float s = 0.f;
#pragma unroll
        for (int w = 0; w < 8; w++) s += scol[w][col];
        g_colpart[(size_t)blockIdx.x * N + col] = s;
    }
}

// ---------------------------------------------------------------------------
// Pass 2: third-order term. Block (g, chunk): rows row = g + 128*k share ONE
// 2 KB sim window kept in registers. E rows staged via cp.async through a
// per-warp 4-stage smem ring (no register double-buffers, no syncthreads in
// the loop). Staging restripes lane data so LDS.128 reads are conflict-free.
// ---------------------------------------------------------------------------
__device__ __forceinline__ float block_sum_256(float v, float* sh) {
    const int tid = threadIdx.x;
    sh[tid] = v; __syncthreads();
#pragma unroll
    for (int st = 128; st > 0; st >>= 1) {
        if (tid < st) sh[tid] += sh[tid + st];
        __syncthreads();
    }
    float r = sh[0]; __syncthreads();
    return r;
}

__device__ __forceinline__ float row_dot(const uint4& e0, const uint4& e1, const float4* w) {
    float s0 = 0.f, s1 = 0.f;
    float2 p;
    p = __half22float2(*reinterpret_cast<const __half2*>(&e0.x)); s0 += p.x * w[0].x + p.y * w[0].y;
    p = __half22float2(*reinterpret_cast<const __half2*>(&e0.y)); s0 += p.x * w[0].z + p.y * w[0].w;
    p = __half22float2(*reinterpret_cast<const __half2*>(&e0.z)); s1 += p.x * w[1].x + p.y * w[1].y;
    p = __half22float2(*reinterpret_cast<const __half2*>(&e0.w)); s1 += p.x * w[1].z + p.y * w[1].w;
    p = __half22float2(*reinterpret_cast<const __half2*>(&e1.x)); s0 += p.x * w[2].x + p.y * w[2].y;
    p = __half22float2(*reinterpret_cast<const __half2*>(&e1.y)); s0 += p.x * w[2].z + p.y * w[2].w;
    p = __half22float2(*reinterpret_cast<const __half2*>(&e1.z)); s1 += p.x * w[3].x + p.y * w[3].y;
    p = __half22float2(*reinterpret_cast<const __half2*>(&e1.w)); s1 += p.x * w[3].z + p.y * w[3].w;
    return s0 + s1;
}

#define STAGES 4

__global__ void __launch_bounds__(256, 4) pass2_kernel(float* __restrict__ out) {
    const int warp = threadIdx.x >> 5;
    const int lane = threadIdx.x & 31;
    const int tid  = threadIdx.x;

    const int g     = blockIdx.x & 127;   // sim window id
    const int chunk = blockIdx.x >> 7;    // which 64 of the 512 rows sharing g

    __shared__ __align__(16) char stage[STAGES][8][1024];   // 32 KB

    // shared sim window in registers: cols lane*16 .. lane*16+15
    float4 w[4];
    {
        const float4* w4 = reinterpret_cast<const float4*>(g_sim + (g << 9)) + lane * 4;
#pragma unroll
        for (int k = 0; k < 4; k++) w[k] = w4[k];
    }

    const int kbase = chunk * 64 + warp * 8;   // k index; row = g + 128*k

    // issue stage j: lane L's 32 B of row (cols [L*16, L*16+16) halves),
    // restriped into two contiguous 512 B halves for conflict-free LDS.128.
    auto issue = [&](int j) {
        const char* src = reinterpret_cast<const char*>(
            g_E + ((size_t)(g + 128 * (kbase + j))) * N) + lane * 32;
        char* dst = &stage[j & (STAGES - 1)][warp][0] + lane * 16;
        __pipeline_memcpy_async(dst,       src,      16);
        __pipeline_memcpy_async(dst + 512, src + 16, 16);
        __pipeline_commit();
    };

    // prologue: 3 stages in flight
    issue(0); issue(1); issue(2);

    float acc = 0.f;
#pragma unroll
    for (int j = 0; j < 8; j++) {
        __pipeline_wait_prior(2);          // stage j complete

        const char* buf = &stage[j & (STAGES - 1)][warp][0];
        uint4 e0 = *reinterpret_cast<const uint4*>(buf + lane * 16);
        uint4 e1 = *reinterpret_cast<const uint4*>(buf + 512 + lane * 16);

        if (j + 3 < 8) issue(j + 3);
        else           __pipeline_commit();   // keep group count uniform

        float sdv = row_dot(e0, e1, w);
#pragma unroll
        for (int o = 16; o; o >>= 1) sdv += __shfl_xor_sync(0xffffffffu, sdv, o);

        if (lane == 0)
            acc += fmaxf(sdv, EPSF) * fmaxf(__logf(sdv), EPSF);
    }
    __pipeline_wait_prior(0);

    // this block's 64-element chunk of sim: consistency + second-order
    float cl = 0.f, so = 0.f;
    if (tid < 64) {
        float s = g_sim[blockIdx.x * 64 + tid];
        float l = __logf(s);
        cl = fmaxf(l, -100.f);
        so = fmaxf(s, EPSF) * fmaxf(l, EPSF);
    }

    // column reduction: blocks 0..511 each own one column of g_colpart
    float cs2 = 0.f;
    if (blockIdx.x < N) {
        for (int b2 = tid; b2 < BLOCKS1; b2 += 256)
            cs2 += g_colpart[(size_t)b2 * N + blockIdx.x];
    }

    __shared__ float sh[256];
    __shared__ float sw[8];
    if (lane == 0) sw[warp] = acc;

    float cl_sum = block_sum_256(cl, sh);
    float so_sum = block_sum_256(so, sh);
    float cs_sum = block_sum_256(cs2, sh);

    if (tid == 0) {
        float t = 0.f;
#pragma unroll
        for (int w2 = 0; w2 < 8; w2++) t += sw[w2];
        g_thirdpart[blockIdx.x] = t;
        g_clpart[blockIdx.x] = cl_sum;
        g_sopart[blockIdx.x] = so_sum;
        if (blockIdx.x < N) g_colsum[blockIdx.x] = cs_sum;
    }

    // ---- last-block final combine ----
    __shared__ int s_last;
    __threadfence();
    if (tid == 0) s_last = (atomicAdd(&g_count, 1u) == BLOCKS2 - 1u) ? 1 : 0;
    __syncthreads();
    if (!s_last) return;
    __threadfence();

    float th = 0.f, clp = 0.f, sop = 0.f;
    for (int i = tid; i < BLOCKS2; i += 256) {
        th  += g_thirdpart[i];
        clp += g_clpart[i];
        sop += g_sopart[i];
    }
    float ent = 0.f;
    for (int i = tid; i < N; i += 256) {
        float pv  = g_colsum[i] * (1.f / (float)B);
        float p_  = fmaxf(pv, EPSF);
        ent += p_ * __logf(p_);
    }

    float th_sum  = block_sum_256(th, sh);
    float clp_sum = block_sum_256(clp, sh);
    float sop_sum = block_sum_256(sop, sh);
    float ent_sum = block_sum_256(ent, sh);

    if (tid == 0) {
        float consistency = -clp_sum * (1.f / (float)B);
        float entropy     = -ent_sum;
        float second      = sop_sum;
        float third       = th_sum * (1.f / (float)N);
        float total = consistency
                    - 2.0f * entropy
                    + (0.25f / (float)N) * second
                    - (0.5f / sqrtf((float)N)) * third;
        out[0] = total;
        out[1] = consistency;
        out[2] = entropy;
        out[3] = second;
        out[4] = third;
        g_count = 0;   // reset for next graph replay
    }
}

// ---------------------------------------------------------------------------
extern "C" void kernel_launch(void* const* d_in, const int* in_sizes, int n_in,
                              void* d_out, int out_size) {
    const float* A  = (const float*)d_in[0];   // anchors  [65536, 512]
    const float* Nb = (const float*)d_in[1];   // neighbors[65536, 512]
    float* out = (float*)d_out;

    pass1_kernel<<<BLOCKS1, 256>>>(A, Nb);
    pass2_kernel<<<BLOCKS2, 256>>>(out);
}

// round 16
// speedup vs baseline: 1.1321x; 1.1321x over previous
#include <cuda_runtime.h>
#include <cuda_fp16.h>
#include <cuda_fp8.h>
#include <math.h>

#define B 65536
#define N 512
#define EPSF 1e-8f
#define BLOCKS1 1024
#define BLOCKS2 2048
#define RPW 8        // rows per warp in pass1 (8 warps/block)
#define E_SCALE 256.0f
#define E_INV_SCALE (1.0f / 256.0f)

// ---------------- scratch (device globals; no allocation allowed) ----------
__device__ __align__(16) float g_sim[B];                    // 256 KB
__device__ __align__(16) unsigned char g_E8[(size_t)B * N]; // 32 MB: fp8(aprob*256)
__device__ float g_colpart[BLOCKS1 * N];                    // 2 MB
__device__ float g_colsum[N];
__device__ float g_thirdpart[BLOCKS2];
__device__ float g_clpart[BLOCKS2];
__device__ float g_sopart[BLOCKS2];
__device__ unsigned int g_count = 0;

__device__ __forceinline__ float warp_max(float v) {
#pragma unroll
    for (int o = 16; o; o >>= 1) v = fmaxf(v, __shfl_xor_sync(0xffffffffu, v, o));
    return v;
}

// ---------------------------------------------------------------------------
// Pass 1: per-row softmax of anchors & neighbors, sim[row], fp8 anchors_prob
// (scaled x256), and per-block column partial sums. A/Nb streamed (__ldcs).
// ---------------------------------------------------------------------------
__global__ void __launch_bounds__(256, 2) pass1_kernel(const float* __restrict__ A,
                                                       const float* __restrict__ Nb) {
    const int warp = threadIdx.x >> 5;
    const int lane = threadIdx.x & 31;
    const int base = (blockIdx.x * 8 + warp) * RPW;

    float4 colacc[4];
#pragma unroll
    for (int c = 0; c < 4; c++) colacc[c] = make_float4(0.f, 0.f, 0.f, 0.f);

    float4 ca[4], cb[4];
    {
        const float4* a4 = reinterpret_cast<const float4*>(A  + (size_t)base * N) + lane;
        const float4* n4 = reinterpret_cast<const float4*>(Nb + (size_t)base * N) + lane;
#pragma unroll
        for (int c = 0; c < 4; c++) { ca[c] = __ldcs(&a4[c * 32]); cb[c] = __ldcs(&n4[c * 32]); }
    }

#pragma unroll
    for (int r = 0; r < RPW; r++) {
        const int row = base + r;

        float4 na[4], nb4[4];
        if (r + 1 < RPW) {
            const float4* a4 = reinterpret_cast<const float4*>(A  + (size_t)(row + 1) * N) + lane;
            const float4* n4 = reinterpret_cast<const float4*>(Nb + (size_t)(row + 1) * N) + lane;
#pragma unroll
            for (int c = 0; c < 4; c++) { na[c] = __ldcs(&a4[c * 32]); nb4[c] = __ldcs(&n4[c * 32]); }
        }

        float ma = -1e30f, mn = -1e30f;
#pragma unroll
        for (int c = 0; c < 4; c++) {
            ma = fmaxf(ma, fmaxf(fmaxf(ca[c].x, ca[c].y), fmaxf(ca[c].z, ca[c].w)));
            mn = fmaxf(mn, fmaxf(fmaxf(cb[c].x, cb[c].y), fmaxf(cb[c].z, cb[c].w)));
        }
        ma = warp_max(ma);
        mn = warp_max(mn);

        float sa0 = 0.f, sa1 = 0.f, sb0 = 0.f, sb1 = 0.f, sd0 = 0.f, sd1 = 0.f;
        float4 ea[4];
#pragma unroll
        for (int c = 0; c < 4; c++) {
            ea[c].x = __expf(ca[c].x - ma); ea[c].y = __expf(ca[c].y - ma);
            ea[c].z = __expf(ca[c].z - ma); ea[c].w = __expf(ca[c].w - ma);
            float ex = __expf(cb[c].x - mn), ey = __expf(cb[c].y - mn);
            float ez = __expf(cb[c].z - mn), ew = __expf(cb[c].w - mn);
            sa0 += ea[c].x + ea[c].y;  sa1 += ea[c].z + ea[c].w;
            sb0 += ex + ey;            sb1 += ez + ew;
            sd0 += ea[c].x * ex + ea[c].y * ey;
            sd1 += ea[c].z * ez + ea[c].w * ew;
        }
        float sa = sa0 + sa1, sb = sb0 + sb1, sd = sd0 + sd1;
#pragma unroll
        for (int o = 16; o; o >>= 1) {
            sa += __shfl_xor_sync(0xffffffffu, sa, o);
            sb += __shfl_xor_sync(0xffffffffu, sb, o);
            sd += __shfl_xor_sync(0xffffffffu, sd, o);
        }

        const float inv  = 1.f / sa;
        const float invs = inv * E_SCALE;
        if (lane == 0) g_sim[row] = sd / (sa * sb);

#pragma unroll
        for (int c = 0; c < 4; c++) {
            float px = ea[c].x * inv, py = ea[c].y * inv;
            float pz = ea[c].z * inv, pw = ea[c].w * inv;
            colacc[c].x += px; colacc[c].y += py;
            colacc[c].z += pz; colacc[c].w += pw;
            // fp8 encode (scaled)
            __nv_fp8x2_storage_t lo = __nv_cvt_float2_to_fp8x2(
                make_float2(ea[c].x * invs, ea[c].y * invs), __NV_SATFINITE, __NV_E4M3);
            __nv_fp8x2_storage_t hi = __nv_cvt_float2_to_fp8x2(
                make_float2(ea[c].z * invs, ea[c].w * invs), __NV_SATFINITE, __NV_E4M3);
            unsigned int pk = (unsigned int)lo | ((unsigned int)hi << 16);
            *reinterpret_cast<unsigned int*>(g_E8 + (size_t)row * N + c * 128 + 4 * lane) = pk;
        }

#pragma unroll
        for (int c = 0; c < 4; c++) { ca[c] = na[c]; cb[c] = nb4[c]; }
    }

    __shared__ float scol[8][N];                 // 16 KB
#pragma unroll
    for (int c = 0; c < 4; c++)
        *reinterpret_cast<float4*>(&scol[warp][c * 128 + 4 * lane]) = colacc[c];
    __syncthreads();

    for (int col = threadIdx.x; col < N; col += 256) {
        float s = 0.f;
#pragma unroll
        for (int w = 0; w < 8; w++) s += scol[w][col];
        g_colpart[(size_t)blockIdx.x * N + col] = s;
    }
}

// ---------------------------------------------------------------------------
// Pass 2 (R13 structure + fp8 + 2x grid): block (g, chunk) handles 32 rows
// row = g + 128*k sharing ONE 2 KB sim window kept in registers. Per row per
// lane: ONE LDG.128 (16 fp8 = 16 cols) + FMAs + warp reduce. Prefetch dist 1.
// ---------------------------------------------------------------------------
__device__ __forceinline__ float block_sum_256(float v, float* sh) {
    const int tid = threadIdx.x;
    sh[tid] = v; __syncthreads();
#pragma unroll
    for (int st = 128; st > 0; st >>= 1) {
        if (tid < st) sh[tid] += sh[tid + st];
        __syncthreads();
    }
    float r = sh[0]; __syncthreads();
    return r;
}

__device__ __forceinline__ float2 fp8x2_to_f2(unsigned short v) {
    __half2_raw hr = __nv_cvt_fp8x2_to_halfraw2((__nv_fp8x2_storage_t)v, __NV_E4M3);
    return __half22float2(*reinterpret_cast<__half2*>(&hr));
}

__device__ __forceinline__ float row_dot8(const uint4& e, const float4* w) {
    float s0 = 0.f, s1 = 0.f;
    float2 p;
    p = fp8x2_to_f2(e.x & 0xffffu); s0 += p.x * w[0].x + p.y * w[0].y;
    p = fp8x2_to_f2(e.x >> 16);     s0 += p.x * w[0].z + p.y * w[0].w;
    p = fp8x2_to_f2(e.y & 0xffffu); s1 += p.x * w[1].x + p.y * w[1].y;
    p = fp8x2_to_f2(e.y >> 16);     s1 += p.x * w[1].z + p.y * w[1].w;
    p = fp8x2_to_f2(e.z & 0xffffu); s0 += p.x * w[2].x + p.y * w[2].y;
    p = fp8x2_to_f2(e.z >> 16);     s0 += p.x * w[2].z + p.y * w[2].w;
    p = fp8x2_to_f2(e.w & 0xffffu); s1 += p.x * w[3].x + p.y * w[3].y;
    p = fp8x2_to_f2(e.w >> 16);     s1 += p.x * w[3].z + p.y * w[3].w;
    return s0 + s1;
}

__global__ void __launch_bounds__(256, 4) pass2_kernel(float* __restrict__ out) {
    const int warp = threadIdx.x >> 5;
    const int lane = threadIdx.x & 31;
    const int tid  = threadIdx.x;

    const int g     = blockIdx.x & 127;   // sim window id
    const int chunk = blockIdx.x >> 7;    // 0..15: which 32 of the 512 rows sharing g

    // shared sim window in registers: cols lane*16 .. lane*16+15
    float4 w[4];
    {
        const float4* w4 = reinterpret_cast<const float4*>(g_sim + (g << 9)) + lane * 4;
#pragma unroll
        for (int k = 0; k < 4; k++) w[k] = w4[k];
    }

    const int kbase = chunk * 32 + warp * 4;   // k index; row = g + 128*k

    // prologue: load first row (one LDG.128 per lane = 16 fp8 cols)
    uint4 e;
    {
        const uint4* ep = reinterpret_cast<const uint4*>(
            g_E8 + ((size_t)(g + 128 * kbase)) * N + lane * 16);
        e = *ep;
    }

    float acc = 0.f;
#pragma unroll
    for (int j = 0; j < 4; j++) {
        uint4 nf;
        if (j + 1 < 4) {
            const uint4* ep = reinterpret_cast<const uint4*>(
                g_E8 + ((size_t)(g + 128 * (kbase + j + 1))) * N + lane * 16);
            nf = *ep;
        }

        float sdv = row_dot8(e, w);
#pragma unroll
        for (int o = 16; o; o >>= 1) sdv += __shfl_xor_sync(0xffffffffu, sdv, o);

        if (lane == 0) {
            float toe = sdv * E_INV_SCALE;
            acc += fmaxf(toe, EPSF) * fmaxf(__logf(toe), EPSF);
        }

        e = nf;
    }

    // this block's 32-element chunk of sim: consistency + second-order
    float cl = 0.f, so = 0.f;
    if (tid < 32) {
        float s = g_sim[blockIdx.x * 32 + tid];
        float l = __logf(s);
        cl = fmaxf(l, -100.f);
        so = fmaxf(s, EPSF) * fmaxf(l, EPSF);
    }

    // column reduction: blocks 0..511 each own one column of g_colpart
    float cs2 = 0.f;
    if (blockIdx.x < N) {
        for (int b2 = tid; b2 < BLOCKS1; b2 += 256)
            cs2 += g_colpart[(size_t)b2 * N + blockIdx.x];
    }

    __shared__ float sh[256];
    __shared__ float sw[8];
    if (lane == 0) sw[warp] = acc;

    float cl_sum = block_sum_256(cl, sh);
    float so_sum = block_sum_256(so, sh);
    float cs_sum = block_sum_256(cs2, sh);

    if (tid == 0) {
        float t = 0.f;
#pragma unroll
        for (int w2 = 0; w2 < 8; w2++) t += sw[w2];
        g_thirdpart[blockIdx.x] = t;
        g_clpart[blockIdx.x] = cl_sum;
        g_sopart[blockIdx.x] = so_sum;
        if (blockIdx.x < N) g_colsum[blockIdx.x] = cs_sum;
    }

    // ---- last-block final combine ----
    __shared__ int s_last;
    __threadfence();
    if (tid == 0) s_last = (atomicAdd(&g_count, 1u) == BLOCKS2 - 1u) ? 1 : 0;
    __syncthreads();
    if (!s_last) return;
    __threadfence();

    float th = 0.f, clp = 0.f, sop = 0.f;
    for (int i = tid; i < BLOCKS2; i += 256) {
        th  += g_thirdpart[i];
        clp += g_clpart[i];
        sop += g_sopart[i];
    }
    float ent = 0.f;
    for (int i = tid; i < N; i += 256) {
        float pv  = g_colsum[i] * (1.f / (float)B);
        float p_  = fmaxf(pv, EPSF);
        ent += p_ * __logf(p_);
    }

    float th_sum  = block_sum_256(th, sh);
    float clp_sum = block_sum_256(clp, sh);
    float sop_sum = block_sum_256(sop, sh);
    float ent_sum = block_sum_256(ent, sh);

    if (tid == 0) {
        float consistency = -clp_sum * (1.f / (float)B);
        float entropy     = -ent_sum;
        float second      = sop_sum;
        float third       = th_sum * (1.f / (float)N);
        float total = consistency
                    - 2.0f * entropy
                    + (0.25f / (float)N) * second
                    - (0.5f / sqrtf((float)N)) * third;
        out[0] = total;
        out[1] = consistency;
        out[2] = entropy;
        out[3] = second;
        out[4] = third;
        g_count = 0;   // reset for next graph replay
    }
}

// ---------------------------------------------------------------------------
extern "C" void kernel_launch(void* const* d_in, const int* in_sizes, int n_in,
                              void* d_out, int out_size) {
    const float* A  = (const float*)d_in[0];   // anchors  [65536, 512]
    const float* Nb = (const float*)d_in[1];   // neighbors[65536, 512]
    float* out = (float*)d_out;

    pass1_kernel<<<BLOCKS1, 256>>>(A, Nb);
    pass2_kernel<<<BLOCKS2, 256>>>(out);
}